// round 6
// baseline (speedup 1.0000x reference)
#include <cuda_runtime.h>
#include <math.h>

#define NMAX 100000
#define EMAX 3200000
#define DIN  128
#define HID  16
#define SCAN_CHUNK 512
#define MAX_SCAN_BLOCKS 1024

// ---- scratch (device globals; allocations forbidden) ----
__device__ int      g_cnt   [NMAX];     // zeroed at end of k_agg2 for next replay
__device__ int      g_start [NMAX];
__device__ int      g_cursor[NMAX];
__device__ float    g_dis   [NMAX];
__device__ float    g_h1    [NMAX * HID];   // pre-scaled by dis[node]
__device__ float    g_h2    [NMAX * 2];     // pre-scaled by dis[node]
__device__ unsigned g_row   [EMAX];
__device__ unsigned g_col   [EMAX];
__device__ unsigned g_srcs  [EMAX];
__device__ int      g_bsum  [MAX_SCAN_BLOCKS];

__device__ __forceinline__ int block_exscan256(int v) {
    __shared__ int wsum[8];
    int lane = threadIdx.x & 31, wid = threadIdx.x >> 5;
    int inc = v;
#pragma unroll
    for (int o = 1; o < 32; o <<= 1) {
        int u = __shfl_up_sync(0xffffffffu, inc, o);
        if (lane >= o) inc += u;
    }
    if (lane == 31) wsum[wid] = inc;
    __syncthreads();
    if (wid == 0) {
        int w = (lane < 8) ? wsum[lane] : 0;
        int winc = w;
#pragma unroll
        for (int o = 1; o < 32; o <<= 1) {
            int u = __shfl_up_sync(0xffffffffu, winc, o);
            if (lane >= o) winc += u;
        }
        if (lane < 8) wsum[lane] = winc - w;
    }
    __syncthreads();
    return wsum[wid] + inc - v;
}

// ---- prep: per-block dtype vote + index convert + degree histogram ----
// (g_cnt arrives zeroed: statically on call 1, by k_agg2 thereafter)
__global__ void __launch_bounds__(256) k_prep(const void* __restrict__ ei,
                                              long long e, int n) {
    // 256-sample dtype vote on the first 2KB (L2-broadcast, consistent everywhere):
    // int64 view of int32 data is "valid" only if 256 high words are all zero.
    long long s = ((const long long*)ei)[threadIdx.x];
    int is64 = __syncthreads_and(s >= 0 && s < n);

    long long i = blockIdx.x * 256LL + threadIdx.x;
    if (i >= e) return;
    unsigned r, c;
    if (is64) {
        r = (unsigned)((const long long*)ei)[i];
        c = (unsigned)((const long long*)ei)[e + i];
    } else {
        r = ((const unsigned*)ei)[i];
        c = ((const unsigned*)ei)[e + i];
    }
    g_row[i] = r;
    g_col[i] = c;
    atomicAdd(&g_cnt[c], 1);
}

// ---- scan A: per-block sums ----
__global__ void k_scanA(int n) {
    int base = blockIdx.x * SCAN_CHUNK;
    int t = threadIdx.x;
    int i0 = base + 2 * t;
    int s = 0;
    if (i0     < n) s += g_cnt[i0];
    if (i0 + 1 < n) s += g_cnt[i0 + 1];
    __shared__ int sh[8];
    int lane = t & 31, wid = t >> 5;
#pragma unroll
    for (int o = 16; o > 0; o >>= 1) s += __shfl_down_sync(0xffffffffu, s, o);
    if (lane == 0) sh[wid] = s;
    __syncthreads();
    if (t == 0) {
        int tot = 0;
#pragma unroll
        for (int w = 0; w < 8; w++) tot += sh[w];
        g_bsum[blockIdx.x] = tot;
    }
}

// ---- scan C: per-block bsum prefix + element offsets + cursor init ----
__global__ void k_scanC(int n, int nb) {
    __shared__ int sh[8];
    __shared__ int s_boff;
    int t = threadIdx.x;
    int lane = t & 31, wid = t >> 5;
    int p = 0;
    for (int j = t; j < blockIdx.x; j += 256) p += g_bsum[j];
#pragma unroll
    for (int o = 16; o > 0; o >>= 1) p += __shfl_down_sync(0xffffffffu, p, o);
    if (lane == 0) sh[wid] = p;
    __syncthreads();
    if (t == 0) {
        int tot = 0;
#pragma unroll
        for (int w = 0; w < 8; w++) tot += sh[w];
        s_boff = tot;
    }
    __syncthreads();
    int boff = s_boff;
    __syncthreads();

    int base = blockIdx.x * SCAN_CHUNK;
    int i0 = base + 2 * t;
    int c0 = (i0     < n) ? g_cnt[i0]     : 0;
    int c1 = (i0 + 1 < n) ? g_cnt[i0 + 1] : 0;
    int ex = block_exscan256(c0 + c1) + boff;
    if (i0 < n)     { g_start[i0]     = ex;      g_cursor[i0]     = ex; }
    if (i0 + 1 < n) { g_start[i0 + 1] = ex + c0; g_cursor[i0 + 1] = ex + c0; }
}

// ---- merged: CSR placement (blocks < nb_place) || gemm1 (remaining blocks) ----
// Independent after scanC; merging overlaps atomic-latency with FMA work.
__global__ void __launch_bounds__(256) k_place_gemm1(const float* __restrict__ x,
                                                     const float* __restrict__ W1,
                                                     int n, long long e, int nb_place) {
    __shared__ float sW[DIN * HID];
    if (blockIdx.x < nb_place) {
        long long i = (long long)blockIdx.x * 256 + threadIdx.x;
        if (i >= e) return;
        unsigned c = g_col[i];
        int pos = atomicAdd(&g_cursor[c], 1);
        g_srcs[pos] = g_row[i];
        return;
    }
    int tid = threadIdx.x;
    for (int i = tid; i < DIN * HID; i += 256) sW[i] = W1[i];
    __syncthreads();
    int t  = (blockIdx.x - nb_place) * 256 + tid;
    int n0 = t * 2, n1 = t * 2 + 1;
    if (n0 >= n) return;
    bool has1 = (n1 < n);
    const float4* xr0 = (const float4*)(x + (long long)n0 * DIN);
    const float4* xr1 = (const float4*)(x + (long long)(has1 ? n1 : n0) * DIN);

    float aA[HID], aB[HID];
#pragma unroll
    for (int c = 0; c < HID; c++) { aA[c] = 0.f; aB[c] = 0.f; }

#pragma unroll 4
    for (int k4 = 0; k4 < DIN / 4; k4++) {
        float4 xa = xr0[k4];
        float4 xb = xr1[k4];
        float xav[4] = {xa.x, xa.y, xa.z, xa.w};
        float xbv[4] = {xb.x, xb.y, xb.z, xb.w};
#pragma unroll
        for (int j = 0; j < 4; j++) {
            const float4* wr = (const float4*)&sW[(k4 * 4 + j) * HID];
            float4 w0 = wr[0], w1 = wr[1], w2 = wr[2], w3 = wr[3];
            float fa = xav[j], fb = xbv[j];
            aA[0] += fa*w0.x; aA[1] += fa*w0.y; aA[2] += fa*w0.z; aA[3] += fa*w0.w;
            aA[4] += fa*w1.x; aA[5] += fa*w1.y; aA[6] += fa*w1.z; aA[7] += fa*w1.w;
            aA[8] += fa*w2.x; aA[9] += fa*w2.y; aA[10]+= fa*w2.z; aA[11]+= fa*w2.w;
            aA[12]+= fa*w3.x; aA[13]+= fa*w3.y; aA[14]+= fa*w3.z; aA[15]+= fa*w3.w;
            aB[0] += fb*w0.x; aB[1] += fb*w0.y; aB[2] += fb*w0.z; aB[3] += fb*w0.w;
            aB[4] += fb*w1.x; aB[5] += fb*w1.y; aB[6] += fb*w1.z; aB[7] += fb*w1.w;
            aB[8] += fb*w2.x; aB[9] += fb*w2.y; aB[10]+= fb*w2.z; aB[11]+= fb*w2.w;
            aB[12]+= fb*w3.x; aB[13]+= fb*w3.y; aB[14]+= fb*w3.z; aB[15]+= fb*w3.w;
        }
    }

    float d0 = rsqrtf((float)(g_cnt[n0] + 1));
    g_dis[n0] = d0;
#pragma unroll
    for (int j = 0; j < 4; j++)
        *(float4*)&g_h1[(long long)n0 * HID + 4*j] =
            make_float4(aA[4*j]*d0, aA[4*j+1]*d0, aA[4*j+2]*d0, aA[4*j+3]*d0);
    if (has1) {
        float d1 = rsqrtf((float)(g_cnt[n1] + 1));
        g_dis[n1] = d1;
#pragma unroll
        for (int j = 0; j < 4; j++)
            *(float4*)&g_h1[(long long)n1 * HID + 4*j] =
                make_float4(aB[4*j]*d1, aB[4*j+1]*d1, aB[4*j+2]*d1, aB[4*j+3]*d1);
    }
}

// ---- layer-1 aggregation: 16 lanes/node = 4 edges x 4 col-quads, LDG.128 ----
__global__ void __launch_bounds__(256) k_agg1(const float* __restrict__ b1,
                                              const float* __restrict__ W2, int n) {
    int t = blockIdx.x * 256 + threadIdx.x;
    int v  = t >> 4;
    int l  = t & 15;
    int g  = l >> 2;         // edge subgroup 0..3
    int c4 = l & 3;          // column quad
    bool live = (v < n);
    int vv = live ? v : (n - 1);

    float dv    = g_dis[vv];
    int   start = g_start[vv];
    int   cnt   = g_cnt[vv];

    float4 A = make_float4(0.f, 0.f, 0.f, 0.f);
    float4 B = make_float4(0.f, 0.f, 0.f, 0.f);
    int k = 0;
    for (; k + 8 <= cnt; k += 8) {
        unsigned s0 = g_srcs[start + k + g];
        unsigned s1 = g_srcs[start + k + 4 + g];
        float4 h0 = *(const float4*)&g_h1[(long long)s0 * HID + c4 * 4];
        float4 h1 = *(const float4*)&g_h1[(long long)s1 * HID + c4 * 4];
        A.x += h0.x; A.y += h0.y; A.z += h0.z; A.w += h0.w;
        B.x += h1.x; B.y += h1.y; B.z += h1.z; B.w += h1.w;
    }
    if (k + g < cnt) {
        unsigned s = g_srcs[start + k + g];
        float4 h = *(const float4*)&g_h1[(long long)s * HID + c4 * 4];
        A.x += h.x; A.y += h.y; A.z += h.z; A.w += h.w;
    }
    if (k + 4 + g < cnt) {
        unsigned s = g_srcs[start + k + 4 + g];
        float4 h = *(const float4*)&g_h1[(long long)s * HID + c4 * 4];
        B.x += h.x; B.y += h.y; B.z += h.z; B.w += h.w;
    }
    A.x += B.x; A.y += B.y; A.z += B.z; A.w += B.w;

    // fold edge-subgroups: lanes {c4, c4+4, c4+8, c4+12} -> lane c4
#pragma unroll
    for (int o = 8; o >= 4; o >>= 1) {
        A.x += __shfl_down_sync(0xffffffffu, A.x, o, 16);
        A.y += __shfl_down_sync(0xffffffffu, A.y, o, 16);
        A.z += __shfl_down_sync(0xffffffffu, A.z, o, 16);
        A.w += __shfl_down_sync(0xffffffffu, A.w, o, 16);
    }

    float p0 = 0.f, p1 = 0.f;
    if (l < 4) {   // lane l holds col-quad l
        float4 self = *(const float4*)&g_h1[(long long)vv * HID + l * 4];
        float a0 = fmaxf(dv * (A.x + self.x) + __ldg(&b1[l*4+0]), 0.f);
        float a1 = fmaxf(dv * (A.y + self.y) + __ldg(&b1[l*4+1]), 0.f);
        float a2 = fmaxf(dv * (A.z + self.z) + __ldg(&b1[l*4+2]), 0.f);
        float a3 = fmaxf(dv * (A.w + self.w) + __ldg(&b1[l*4+3]), 0.f);
        p0 = a0*__ldg(&W2[(l*4+0)*2+0]) + a1*__ldg(&W2[(l*4+1)*2+0])
           + a2*__ldg(&W2[(l*4+2)*2+0]) + a3*__ldg(&W2[(l*4+3)*2+0]);
        p1 = a0*__ldg(&W2[(l*4+0)*2+1]) + a1*__ldg(&W2[(l*4+1)*2+1])
           + a2*__ldg(&W2[(l*4+2)*2+1]) + a3*__ldg(&W2[(l*4+3)*2+1]);
    }
    p0 += __shfl_down_sync(0xffffffffu, p0, 2, 16);
    p1 += __shfl_down_sync(0xffffffffu, p1, 2, 16);
    p0 += __shfl_down_sync(0xffffffffu, p0, 1, 16);
    p1 += __shfl_down_sync(0xffffffffu, p1, 1, 16);
    if (live && l == 0) {
        g_h2[(long long)v * 2 + 0] = p0 * dv;
        g_h2[(long long)v * 2 + 1] = p1 * dv;
    }
}

// ---- layer-2 aggregation + log_softmax; zeroes g_cnt for the next replay ----
__global__ void __launch_bounds__(256) k_agg2(const float* __restrict__ b2,
                                              float* __restrict__ out, int n) {
    int t = blockIdx.x * 256 + threadIdx.x;
    int v = t >> 3;
    int l = t & 7;
    bool live = (v < n);
    int vv = live ? v : (n - 1);

    float dv    = g_dis[vv];
    int   start = g_start[vv];
    int   cnt   = g_cnt[vv];
    float a0 = 0.f, a1 = 0.f, b0 = 0.f, b1v = 0.f;
    int k = l;
    for (; k + 8 < cnt; k += 16) {
        unsigned s0 = g_srcs[start + k];
        unsigned s1 = g_srcs[start + k + 8];
        float2 h0 = *(const float2*)&g_h2[(long long)s0 * 2];
        float2 h1 = *(const float2*)&g_h2[(long long)s1 * 2];
        a0 += h0.x; a1 += h0.y;
        b0 += h1.x; b1v += h1.y;
    }
    if (k < cnt) {
        unsigned s = g_srcs[start + k];
        float2 h = *(const float2*)&g_h2[(long long)s * 2];
        a0 += h.x; a1 += h.y;
    }
    a0 += b0; a1 += b1v;
#pragma unroll
    for (int o = 4; o > 0; o >>= 1) {
        a0 += __shfl_down_sync(0xffffffffu, a0, o, 8);
        a1 += __shfl_down_sync(0xffffffffu, a1, o, 8);
    }
    if (live && l == 0) {
        float2 hs = *(const float2*)&g_h2[(long long)v * 2];
        float v0 = dv * (a0 + hs.x) + __ldg(&b2[0]);
        float v1 = dv * (a1 + hs.y) + __ldg(&b2[1]);
        float m  = fmaxf(v0, v1);
        float lse = m + logf(expf(v0 - m) + expf(v1 - m));
        out[(long long)v * 2 + 0] = v0 - lse;
        out[(long long)v * 2 + 1] = v1 - lse;
        g_cnt[v] = 0;                      // ready for next replay
    }
}

extern "C" void kernel_launch(void* const* d_in, const int* in_sizes, int n_in,
                              void* d_out, int out_size) {
    const float* x  = (const float*)d_in[0];
    const void*  ei = d_in[1];
    const float* W1 = (const float*)d_in[2];
    const float* b1 = (const float*)d_in[3];
    const float* W2 = (const float*)d_in[4];
    const float* b2 = (const float*)d_in[5];
    float* out = (float*)d_out;

    int n = in_sizes[0] / DIN;
    long long e = (long long)in_sizes[1] / 2;

    int nb_e    = (int)((e + 255) / 256);
    int nb_scan = (n + SCAN_CHUNK - 1) / SCAN_CHUNK;
    int nb_g    = ((n + 1) / 2 + 255) / 256;
    int nb_a1   = (n * 16 + 255) / 256;
    int nb_a2   = (n * 8 + 255) / 256;

    k_prep       <<<nb_e,        256>>>(ei, e, n);
    k_scanA      <<<nb_scan,     256>>>(n);
    k_scanC      <<<nb_scan,     256>>>(n, nb_scan);
    k_place_gemm1<<<nb_e + nb_g, 256>>>(x, W1, n, e, nb_e);
    k_agg1       <<<nb_a1,       256>>>(b1, W2, n);
    k_agg2       <<<nb_a2,       256>>>(b2, out, n);
}

// round 7
// speedup vs baseline: 1.0355x; 1.0355x over previous
#include <cuda_runtime.h>
#include <math.h>

#define NMAX 100000
#define EMAX 3200000
#define DIN  128
#define HID  16
#define SCAN_CHUNK 512
#define MAX_SCAN_BLOCKS 1024

// ---- scratch (device globals; allocations forbidden) ----
__device__ int      g_cnt   [NMAX];     // zeroed at end of k_agg2 for next replay
__device__ int      g_start [NMAX];
__device__ int      g_cursor[NMAX];
__device__ float    g_dis   [NMAX];
__device__ float    g_h1    [NMAX * HID];   // pre-scaled by dis[node]
__device__ float    g_h2    [NMAX * 2];     // pre-scaled by dis[node]
__device__ unsigned g_row   [EMAX];
__device__ unsigned g_col   [EMAX];
__device__ unsigned g_srcs  [EMAX];
__device__ int      g_bsum  [MAX_SCAN_BLOCKS];

__device__ __forceinline__ int block_exscan256(int v) {
    __shared__ int wsum[8];
    int lane = threadIdx.x & 31, wid = threadIdx.x >> 5;
    int inc = v;
#pragma unroll
    for (int o = 1; o < 32; o <<= 1) {
        int u = __shfl_up_sync(0xffffffffu, inc, o);
        if (lane >= o) inc += u;
    }
    if (lane == 31) wsum[wid] = inc;
    __syncthreads();
    if (wid == 0) {
        int w = (lane < 8) ? wsum[lane] : 0;
        int winc = w;
#pragma unroll
        for (int o = 1; o < 32; o <<= 1) {
            int u = __shfl_up_sync(0xffffffffu, winc, o);
            if (lane >= o) winc += u;
        }
        if (lane < 8) wsum[lane] = winc - w;
    }
    __syncthreads();
    return wsum[wid] + inc - v;
}

// ---- prep: per-block dtype vote + index convert + degree histogram ----
__global__ void __launch_bounds__(256) k_prep(const void* __restrict__ ei,
                                              long long e, int n) {
    long long s = ((const long long*)ei)[threadIdx.x];
    int is64 = __syncthreads_and(s >= 0 && s < n);

    long long i = blockIdx.x * 256LL + threadIdx.x;
    if (i >= e) return;
    unsigned r, c;
    if (is64) {
        r = (unsigned)((const long long*)ei)[i];
        c = (unsigned)((const long long*)ei)[e + i];
    } else {
        r = ((const unsigned*)ei)[i];
        c = ((const unsigned*)ei)[e + i];
    }
    g_row[i] = r;
    g_col[i] = c;
    atomicAdd(&g_cnt[c], 1);
}

// ---- scan A: per-block sums ----
__global__ void k_scanA(int n) {
    int base = blockIdx.x * SCAN_CHUNK;
    int t = threadIdx.x;
    int i0 = base + 2 * t;
    int s = 0;
    if (i0     < n) s += g_cnt[i0];
    if (i0 + 1 < n) s += g_cnt[i0 + 1];
    __shared__ int sh[8];
    int lane = t & 31, wid = t >> 5;
#pragma unroll
    for (int o = 16; o > 0; o >>= 1) s += __shfl_down_sync(0xffffffffu, s, o);
    if (lane == 0) sh[wid] = s;
    __syncthreads();
    if (t == 0) {
        int tot = 0;
#pragma unroll
        for (int w = 0; w < 8; w++) tot += sh[w];
        g_bsum[blockIdx.x] = tot;
    }
}

// ---- scan C: per-block bsum prefix + element offsets + cursor init ----
__global__ void k_scanC(int n, int nb) {
    __shared__ int sh[8];
    __shared__ int s_boff;
    int t = threadIdx.x;
    int lane = t & 31, wid = t >> 5;
    int p = 0;
    for (int j = t; j < blockIdx.x; j += 256) p += g_bsum[j];
#pragma unroll
    for (int o = 16; o > 0; o >>= 1) p += __shfl_down_sync(0xffffffffu, p, o);
    if (lane == 0) sh[wid] = p;
    __syncthreads();
    if (t == 0) {
        int tot = 0;
#pragma unroll
        for (int w = 0; w < 8; w++) tot += sh[w];
        s_boff = tot;
    }
    __syncthreads();
    int boff = s_boff;
    __syncthreads();

    int base = blockIdx.x * SCAN_CHUNK;
    int i0 = base + 2 * t;
    int c0 = (i0     < n) ? g_cnt[i0]     : 0;
    int c1 = (i0 + 1 < n) ? g_cnt[i0 + 1] : 0;
    int ex = block_exscan256(c0 + c1) + boff;
    if (i0 < n)     { g_start[i0]     = ex;      g_cursor[i0]     = ex; }
    if (i0 + 1 < n) { g_start[i0 + 1] = ex + c0; g_cursor[i0 + 1] = ex + c0; }
}

// ---- CSR placement: lean (low regs, max occupancy), 2 edges/thread ----
__global__ void __launch_bounds__(256) k_place(long long e) {
    long long i = blockIdx.x * 512LL + threadIdx.x;
    if (i < e) {
        unsigned c = g_col[i];
        int pos = atomicAdd(&g_cursor[c], 1);
        g_srcs[pos] = g_row[i];
    }
    i += 256;
    if (i < e) {
        unsigned c = g_col[i];
        int pos = atomicAdd(&g_cursor[c], 1);
        g_srcs[pos] = g_row[i];
    }
}

// ---- h1s = (x @ W1) * dis ; dis = rsqrt(cnt+1) fused ----
__global__ void __launch_bounds__(256) k_gemm1(const float* __restrict__ x,
                                               const float* __restrict__ W1, int n) {
    __shared__ float sW[DIN * HID];
    int tid = threadIdx.x;
    for (int i = tid; i < DIN * HID; i += 256) sW[i] = W1[i];
    __syncthreads();
    int t  = blockIdx.x * 256 + tid;
    int n0 = t * 2, n1 = t * 2 + 1;
    if (n0 >= n) return;
    bool has1 = (n1 < n);
    const float4* xr0 = (const float4*)(x + (long long)n0 * DIN);
    const float4* xr1 = (const float4*)(x + (long long)(has1 ? n1 : n0) * DIN);

    float aA[HID], aB[HID];
#pragma unroll
    for (int c = 0; c < HID; c++) { aA[c] = 0.f; aB[c] = 0.f; }

#pragma unroll 4
    for (int k4 = 0; k4 < DIN / 4; k4++) {
        float4 xa = xr0[k4];
        float4 xb = xr1[k4];
        float xav[4] = {xa.x, xa.y, xa.z, xa.w};
        float xbv[4] = {xb.x, xb.y, xb.z, xb.w};
#pragma unroll
        for (int j = 0; j < 4; j++) {
            const float4* wr = (const float4*)&sW[(k4 * 4 + j) * HID];
            float4 w0 = wr[0], w1 = wr[1], w2 = wr[2], w3 = wr[3];
            float fa = xav[j], fb = xbv[j];
            aA[0] += fa*w0.x; aA[1] += fa*w0.y; aA[2] += fa*w0.z; aA[3] += fa*w0.w;
            aA[4] += fa*w1.x; aA[5] += fa*w1.y; aA[6] += fa*w1.z; aA[7] += fa*w1.w;
            aA[8] += fa*w2.x; aA[9] += fa*w2.y; aA[10]+= fa*w2.z; aA[11]+= fa*w2.w;
            aA[12]+= fa*w3.x; aA[13]+= fa*w3.y; aA[14]+= fa*w3.z; aA[15]+= fa*w3.w;
            aB[0] += fb*w0.x; aB[1] += fb*w0.y; aB[2] += fb*w0.z; aB[3] += fb*w0.w;
            aB[4] += fb*w1.x; aB[5] += fb*w1.y; aB[6] += fb*w1.z; aB[7] += fb*w1.w;
            aB[8] += fb*w2.x; aB[9] += fb*w2.y; aB[10]+= fb*w2.z; aB[11]+= fb*w2.w;
            aB[12]+= fb*w3.x; aB[13]+= fb*w3.y; aB[14]+= fb*w3.z; aB[15]+= fb*w3.w;
        }
    }

    float d0 = rsqrtf((float)(g_cnt[n0] + 1));
    g_dis[n0] = d0;
#pragma unroll
    for (int j = 0; j < 4; j++)
        *(float4*)&g_h1[(long long)n0 * HID + 4*j] =
            make_float4(aA[4*j]*d0, aA[4*j+1]*d0, aA[4*j+2]*d0, aA[4*j+3]*d0);
    if (has1) {
        float d1 = rsqrtf((float)(g_cnt[n1] + 1));
        g_dis[n1] = d1;
#pragma unroll
        for (int j = 0; j < 4; j++)
            *(float4*)&g_h1[(long long)n1 * HID + 4*j] =
                make_float4(aB[4*j]*d1, aB[4*j+1]*d1, aB[4*j+2]*d1, aB[4*j+3]*d1);
    }
}

// ---- layer-1 aggregation: 16 lanes/node = 4 edges x 4 col-quads, LDG.128 ----
__global__ void __launch_bounds__(256) k_agg1(const float* __restrict__ b1,
                                              const float* __restrict__ W2, int n) {
    int t = blockIdx.x * 256 + threadIdx.x;
    int v  = t >> 4;
    int l  = t & 15;
    int g  = l >> 2;         // edge subgroup 0..3
    int c4 = l & 3;          // column quad
    bool live = (v < n);
    int vv = live ? v : (n - 1);

    float dv    = g_dis[vv];
    int   start = g_start[vv];
    int   cnt   = g_cnt[vv];

    float4 A = make_float4(0.f, 0.f, 0.f, 0.f);
    float4 B = make_float4(0.f, 0.f, 0.f, 0.f);
    int k = 0;
    for (; k + 8 <= cnt; k += 8) {
        unsigned s0 = g_srcs[start + k + g];
        unsigned s1 = g_srcs[start + k + 4 + g];
        float4 h0 = *(const float4*)&g_h1[(long long)s0 * HID + c4 * 4];
        float4 h1 = *(const float4*)&g_h1[(long long)s1 * HID + c4 * 4];
        A.x += h0.x; A.y += h0.y; A.z += h0.z; A.w += h0.w;
        B.x += h1.x; B.y += h1.y; B.z += h1.z; B.w += h1.w;
    }
    if (k + g < cnt) {
        unsigned s = g_srcs[start + k + g];
        float4 h = *(const float4*)&g_h1[(long long)s * HID + c4 * 4];
        A.x += h.x; A.y += h.y; A.z += h.z; A.w += h.w;
    }
    if (k + 4 + g < cnt) {
        unsigned s = g_srcs[start + k + 4 + g];
        float4 h = *(const float4*)&g_h1[(long long)s * HID + c4 * 4];
        B.x += h.x; B.y += h.y; B.z += h.z; B.w += h.w;
    }
    A.x += B.x; A.y += B.y; A.z += B.z; A.w += B.w;

#pragma unroll
    for (int o = 8; o >= 4; o >>= 1) {
        A.x += __shfl_down_sync(0xffffffffu, A.x, o, 16);
        A.y += __shfl_down_sync(0xffffffffu, A.y, o, 16);
        A.z += __shfl_down_sync(0xffffffffu, A.z, o, 16);
        A.w += __shfl_down_sync(0xffffffffu, A.w, o, 16);
    }

    float p0 = 0.f, p1 = 0.f;
    if (l < 4) {
        float4 self = *(const float4*)&g_h1[(long long)vv * HID + l * 4];
        float a0 = fmaxf(dv * (A.x + self.x) + __ldg(&b1[l*4+0]), 0.f);
        float a1 = fmaxf(dv * (A.y + self.y) + __ldg(&b1[l*4+1]), 0.f);
        float a2 = fmaxf(dv * (A.z + self.z) + __ldg(&b1[l*4+2]), 0.f);
        float a3 = fmaxf(dv * (A.w + self.w) + __ldg(&b1[l*4+3]), 0.f);
        p0 = a0*__ldg(&W2[(l*4+0)*2+0]) + a1*__ldg(&W2[(l*4+1)*2+0])
           + a2*__ldg(&W2[(l*4+2)*2+0]) + a3*__ldg(&W2[(l*4+3)*2+0]);
        p1 = a0*__ldg(&W2[(l*4+0)*2+1]) + a1*__ldg(&W2[(l*4+1)*2+1])
           + a2*__ldg(&W2[(l*4+2)*2+1]) + a3*__ldg(&W2[(l*4+3)*2+1]);
    }
    p0 += __shfl_down_sync(0xffffffffu, p0, 2, 16);
    p1 += __shfl_down_sync(0xffffffffu, p1, 2, 16);
    p0 += __shfl_down_sync(0xffffffffu, p0, 1, 16);
    p1 += __shfl_down_sync(0xffffffffu, p1, 1, 16);
    if (live && l == 0) {
        g_h2[(long long)v * 2 + 0] = p0 * dv;
        g_h2[(long long)v * 2 + 1] = p1 * dv;
    }
}

// ---- layer-2 aggregation + log_softmax; zeroes g_cnt for the next replay ----
__global__ void __launch_bounds__(256) k_agg2(const float* __restrict__ b2,
                                              float* __restrict__ out, int n) {
    int t = blockIdx.x * 256 + threadIdx.x;
    int v = t >> 3;
    int l = t & 7;
    bool live = (v < n);
    int vv = live ? v : (n - 1);

    float dv    = g_dis[vv];
    int   start = g_start[vv];
    int   cnt   = g_cnt[vv];
    float a0 = 0.f, a1 = 0.f, b0 = 0.f, b1v = 0.f;
    int k = l;
    for (; k + 8 < cnt; k += 16) {
        unsigned s0 = g_srcs[start + k];
        unsigned s1 = g_srcs[start + k + 8];
        float2 h0 = *(const float2*)&g_h2[(long long)s0 * 2];
        float2 h1 = *(const float2*)&g_h2[(long long)s1 * 2];
        a0 += h0.x; a1 += h0.y;
        b0 += h1.x; b1v += h1.y;
    }
    if (k < cnt) {
        unsigned s = g_srcs[start + k];
        float2 h = *(const float2*)&g_h2[(long long)s * 2];
        a0 += h.x; a1 += h.y;
    }
    a0 += b0; a1 += b1v;
#pragma unroll
    for (int o = 4; o > 0; o >>= 1) {
        a0 += __shfl_down_sync(0xffffffffu, a0, o, 8);
        a1 += __shfl_down_sync(0xffffffffu, a1, o, 8);
    }
    if (live && l == 0) {
        float2 hs = *(const float2*)&g_h2[(long long)v * 2];
        float v0 = dv * (a0 + hs.x) + __ldg(&b2[0]);
        float v1 = dv * (a1 + hs.y) + __ldg(&b2[1]);
        float m  = fmaxf(v0, v1);
        float lse = m + logf(expf(v0 - m) + expf(v1 - m));
        out[(long long)v * 2 + 0] = v0 - lse;
        out[(long long)v * 2 + 1] = v1 - lse;
        g_cnt[v] = 0;                      // ready for next replay
    }
}

extern "C" void kernel_launch(void* const* d_in, const int* in_sizes, int n_in,
                              void* d_out, int out_size) {
    const float* x  = (const float*)d_in[0];
    const void*  ei = d_in[1];
    const float* W1 = (const float*)d_in[2];
    const float* b1 = (const float*)d_in[3];
    const float* W2 = (const float*)d_in[4];
    const float* b2 = (const float*)d_in[5];
    float* out = (float*)d_out;

    int n = in_sizes[0] / DIN;
    long long e = (long long)in_sizes[1] / 2;

    int nb_e     = (int)((e + 255) / 256);
    int nb_place = (int)((e + 511) / 512);
    int nb_scan  = (n + SCAN_CHUNK - 1) / SCAN_CHUNK;
    int nb_g     = ((n + 1) / 2 + 255) / 256;
    int nb_a1    = (n * 16 + 255) / 256;
    int nb_a2    = (n * 8 + 255) / 256;

    k_prep  <<<nb_e,     256>>>(ei, e, n);
    k_scanA <<<nb_scan,  256>>>(n);
    k_scanC <<<nb_scan,  256>>>(n, nb_scan);
    k_place <<<nb_place, 256>>>(e);
    k_gemm1 <<<nb_g,     256>>>(x, W1, n);
    k_agg1  <<<nb_a1,    256>>>(b1, W2, n);
    k_agg2  <<<nb_a2,    256>>>(b2, out, n);
}

// round 8
// speedup vs baseline: 1.0965x; 1.0589x over previous
#include <cuda_runtime.h>
#include <math.h>

#define NMAX 100000
#define EMAX 3200000
#define DIN  128
#define HID  16
#define SCAN_CHUNK 512
#define MAX_SCAN_BLOCKS 1024

// ---- scratch (device globals; allocations forbidden) ----
__device__ int      g_cnt  [NMAX];      // zeroed at end of k_agg2 for next replay
__device__ int      g_start[NMAX];
__device__ float    g_dis  [NMAX];
__device__ float    g_h1   [NMAX * HID];   // pre-scaled by dis[node]
__device__ float    g_h2   [NMAX * 2];     // pre-scaled by dis[node]
__device__ unsigned g_row  [EMAX];
__device__ unsigned g_col  [EMAX];
__device__ unsigned g_rank [EMAX];      // arrival rank within target bucket
__device__ unsigned g_srcs [EMAX];
__device__ int      g_bsum [MAX_SCAN_BLOCKS];

__device__ __forceinline__ int block_exscan256(int v) {
    __shared__ int wsum[8];
    int lane = threadIdx.x & 31, wid = threadIdx.x >> 5;
    int inc = v;
#pragma unroll
    for (int o = 1; o < 32; o <<= 1) {
        int u = __shfl_up_sync(0xffffffffu, inc, o);
        if (lane >= o) inc += u;
    }
    if (lane == 31) wsum[wid] = inc;
    __syncthreads();
    if (wid == 0) {
        int w = (lane < 8) ? wsum[lane] : 0;
        int winc = w;
#pragma unroll
        for (int o = 1; o < 32; o <<= 1) {
            int u = __shfl_up_sync(0xffffffffu, winc, o);
            if (lane >= o) winc += u;
        }
        if (lane < 8) wsum[lane] = winc - w;
    }
    __syncthreads();
    return wsum[wid] + inc - v;
}

// ---- prep: dtype vote + index convert + degree histogram + rank capture ----
__global__ void __launch_bounds__(256) k_prep(const void* __restrict__ ei,
                                              long long e, int n) {
    long long s = ((const long long*)ei)[threadIdx.x];
    int is64 = __syncthreads_and(s >= 0 && s < n);

    long long i = blockIdx.x * 256LL + threadIdx.x;
    if (i >= e) return;
    unsigned r, c;
    if (is64) {
        r = (unsigned)((const long long*)ei)[i];
        c = (unsigned)((const long long*)ei)[e + i];
    } else {
        r = ((const unsigned*)ei)[i];
        c = ((const unsigned*)ei)[e + i];
    }
    g_row[i]  = r;
    g_col[i]  = c;
    g_rank[i] = (unsigned)atomicAdd(&g_cnt[c], 1);   // rank within bucket, free
}

// ---- scan A: per-block sums ----
__global__ void k_scanA(int n) {
    int base = blockIdx.x * SCAN_CHUNK;
    int t = threadIdx.x;
    int i0 = base + 2 * t;
    int s = 0;
    if (i0     < n) s += g_cnt[i0];
    if (i0 + 1 < n) s += g_cnt[i0 + 1];
    __shared__ int sh[8];
    int lane = t & 31, wid = t >> 5;
#pragma unroll
    for (int o = 16; o > 0; o >>= 1) s += __shfl_down_sync(0xffffffffu, s, o);
    if (lane == 0) sh[wid] = s;
    __syncthreads();
    if (t == 0) {
        int tot = 0;
#pragma unroll
        for (int w = 0; w < 8; w++) tot += sh[w];
        g_bsum[blockIdx.x] = tot;
    }
}

// ---- scan C: per-block bsum prefix + element offsets ----
__global__ void k_scanC(int n, int nb) {
    __shared__ int sh[8];
    __shared__ int s_boff;
    int t = threadIdx.x;
    int lane = t & 31, wid = t >> 5;
    int p = 0;
    for (int j = t; j < blockIdx.x; j += 256) p += g_bsum[j];
#pragma unroll
    for (int o = 16; o > 0; o >>= 1) p += __shfl_down_sync(0xffffffffu, p, o);
    if (lane == 0) sh[wid] = p;
    __syncthreads();
    if (t == 0) {
        int tot = 0;
#pragma unroll
        for (int w = 0; w < 8; w++) tot += sh[w];
        s_boff = tot;
    }
    __syncthreads();
    int boff = s_boff;
    __syncthreads();

    int base = blockIdx.x * SCAN_CHUNK;
    int i0 = base + 2 * t;
    int c0 = (i0     < n) ? g_cnt[i0]     : 0;
    int c1 = (i0 + 1 < n) ? g_cnt[i0 + 1] : 0;
    int ex = block_exscan256(c0 + c1) + boff;
    if (i0 < n)     g_start[i0]     = ex;
    if (i0 + 1 < n) g_start[i0 + 1] = ex + c0;
}

// ---- CSR placement: NO atomics — pos = start[col] + rank ----
__global__ void __launch_bounds__(256) k_place(long long e) {
    long long i = blockIdx.x * 512LL + threadIdx.x;
    if (i < e) {
        unsigned c = g_col[i];
        g_srcs[g_start[c] + g_rank[i]] = g_row[i];
    }
    i += 256;
    if (i < e) {
        unsigned c = g_col[i];
        g_srcs[g_start[c] + g_rank[i]] = g_row[i];
    }
}

// ---- h1s = (x @ W1) * dis ; dis = rsqrt(cnt+1) fused ----
__global__ void __launch_bounds__(256) k_gemm1(const float* __restrict__ x,
                                               const float* __restrict__ W1, int n) {
    __shared__ float sW[DIN * HID];
    int tid = threadIdx.x;
    for (int i = tid; i < DIN * HID; i += 256) sW[i] = W1[i];
    __syncthreads();
    int t  = blockIdx.x * 256 + tid;
    int n0 = t * 2, n1 = t * 2 + 1;
    if (n0 >= n) return;
    bool has1 = (n1 < n);
    const float4* xr0 = (const float4*)(x + (long long)n0 * DIN);
    const float4* xr1 = (const float4*)(x + (long long)(has1 ? n1 : n0) * DIN);

    float aA[HID], aB[HID];
#pragma unroll
    for (int c = 0; c < HID; c++) { aA[c] = 0.f; aB[c] = 0.f; }

#pragma unroll 4
    for (int k4 = 0; k4 < DIN / 4; k4++) {
        float4 xa = xr0[k4];
        float4 xb = xr1[k4];
        float xav[4] = {xa.x, xa.y, xa.z, xa.w};
        float xbv[4] = {xb.x, xb.y, xb.z, xb.w};
#pragma unroll
        for (int j = 0; j < 4; j++) {
            const float4* wr = (const float4*)&sW[(k4 * 4 + j) * HID];
            float4 w0 = wr[0], w1 = wr[1], w2 = wr[2], w3 = wr[3];
            float fa = xav[j], fb = xbv[j];
            aA[0] += fa*w0.x; aA[1] += fa*w0.y; aA[2] += fa*w0.z; aA[3] += fa*w0.w;
            aA[4] += fa*w1.x; aA[5] += fa*w1.y; aA[6] += fa*w1.z; aA[7] += fa*w1.w;
            aA[8] += fa*w2.x; aA[9] += fa*w2.y; aA[10]+= fa*w2.z; aA[11]+= fa*w2.w;
            aA[12]+= fa*w3.x; aA[13]+= fa*w3.y; aA[14]+= fa*w3.z; aA[15]+= fa*w3.w;
            aB[0] += fb*w0.x; aB[1] += fb*w0.y; aB[2] += fb*w0.z; aB[3] += fb*w0.w;
            aB[4] += fb*w1.x; aB[5] += fb*w1.y; aB[6] += fb*w1.z; aB[7] += fb*w1.w;
            aB[8] += fb*w2.x; aB[9] += fb*w2.y; aB[10]+= fb*w2.z; aB[11]+= fb*w2.w;
            aB[12]+= fb*w3.x; aB[13]+= fb*w3.y; aB[14]+= fb*w3.z; aB[15]+= fb*w3.w;
        }
    }

    float d0 = rsqrtf((float)(g_cnt[n0] + 1));
    g_dis[n0] = d0;
#pragma unroll
    for (int j = 0; j < 4; j++)
        *(float4*)&g_h1[(long long)n0 * HID + 4*j] =
            make_float4(aA[4*j]*d0, aA[4*j+1]*d0, aA[4*j+2]*d0, aA[4*j+3]*d0);
    if (has1) {
        float d1 = rsqrtf((float)(g_cnt[n1] + 1));
        g_dis[n1] = d1;
#pragma unroll
        for (int j = 0; j < 4; j++)
            *(float4*)&g_h1[(long long)n1 * HID + 4*j] =
                make_float4(aB[4*j]*d1, aB[4*j+1]*d1, aB[4*j+2]*d1, aB[4*j+3]*d1);
    }
}

// ---- layer-1 aggregation: 16 lanes/node = 4 edges x 4 col-quads, LDG.128 ----
__global__ void __launch_bounds__(256) k_agg1(const float* __restrict__ b1,
                                              const float* __restrict__ W2, int n) {
    int t = blockIdx.x * 256 + threadIdx.x;
    int v  = t >> 4;
    int l  = t & 15;
    int g  = l >> 2;
    int c4 = l & 3;
    bool live = (v < n);
    int vv = live ? v : (n - 1);

    float dv    = g_dis[vv];
    int   start = g_start[vv];
    int   cnt   = g_cnt[vv];

    float4 A = make_float4(0.f, 0.f, 0.f, 0.f);
    float4 B = make_float4(0.f, 0.f, 0.f, 0.f);
    int k = 0;
    for (; k + 8 <= cnt; k += 8) {
        unsigned s0 = g_srcs[start + k + g];
        unsigned s1 = g_srcs[start + k + 4 + g];
        float4 h0 = *(const float4*)&g_h1[(long long)s0 * HID + c4 * 4];
        float4 h1 = *(const float4*)&g_h1[(long long)s1 * HID + c4 * 4];
        A.x += h0.x; A.y += h0.y; A.z += h0.z; A.w += h0.w;
        B.x += h1.x; B.y += h1.y; B.z += h1.z; B.w += h1.w;
    }
    if (k + g < cnt) {
        unsigned s = g_srcs[start + k + g];
        float4 h = *(const float4*)&g_h1[(long long)s * HID + c4 * 4];
        A.x += h.x; A.y += h.y; A.z += h.z; A.w += h.w;
    }
    if (k + 4 + g < cnt) {
        unsigned s = g_srcs[start + k + 4 + g];
        float4 h = *(const float4*)&g_h1[(long long)s * HID + c4 * 4];
        B.x += h.x; B.y += h.y; B.z += h.z; B.w += h.w;
    }
    A.x += B.x; A.y += B.y; A.z += B.z; A.w += B.w;

#pragma unroll
    for (int o = 8; o >= 4; o >>= 1) {
        A.x += __shfl_down_sync(0xffffffffu, A.x, o, 16);
        A.y += __shfl_down_sync(0xffffffffu, A.y, o, 16);
        A.z += __shfl_down_sync(0xffffffffu, A.z, o, 16);
        A.w += __shfl_down_sync(0xffffffffu, A.w, o, 16);
    }

    float p0 = 0.f, p1 = 0.f;
    if (l < 4) {
        float4 self = *(const float4*)&g_h1[(long long)vv * HID + l * 4];
        float a0 = fmaxf(dv * (A.x + self.x) + __ldg(&b1[l*4+0]), 0.f);
        float a1 = fmaxf(dv * (A.y + self.y) + __ldg(&b1[l*4+1]), 0.f);
        float a2 = fmaxf(dv * (A.z + self.z) + __ldg(&b1[l*4+2]), 0.f);
        float a3 = fmaxf(dv * (A.w + self.w) + __ldg(&b1[l*4+3]), 0.f);
        p0 = a0*__ldg(&W2[(l*4+0)*2+0]) + a1*__ldg(&W2[(l*4+1)*2+0])
           + a2*__ldg(&W2[(l*4+2)*2+0]) + a3*__ldg(&W2[(l*4+3)*2+0]);
        p1 = a0*__ldg(&W2[(l*4+0)*2+1]) + a1*__ldg(&W2[(l*4+1)*2+1])
           + a2*__ldg(&W2[(l*4+2)*2+1]) + a3*__ldg(&W2[(l*4+3)*2+1]);
    }
    p0 += __shfl_down_sync(0xffffffffu, p0, 2, 16);
    p1 += __shfl_down_sync(0xffffffffu, p1, 2, 16);
    p0 += __shfl_down_sync(0xffffffffu, p0, 1, 16);
    p1 += __shfl_down_sync(0xffffffffu, p1, 1, 16);
    if (live && l == 0) {
        g_h2[(long long)v * 2 + 0] = p0 * dv;
        g_h2[(long long)v * 2 + 1] = p1 * dv;
    }
}

// ---- layer-2 aggregation + log_softmax; zeroes g_cnt for the next replay ----
__global__ void __launch_bounds__(256) k_agg2(const float* __restrict__ b2,
                                              float* __restrict__ out, int n) {
    int t = blockIdx.x * 256 + threadIdx.x;
    int v = t >> 3;
    int l = t & 7;
    bool live = (v < n);
    int vv = live ? v : (n - 1);

    float dv    = g_dis[vv];
    int   start = g_start[vv];
    int   cnt   = g_cnt[vv];
    float a0 = 0.f, a1 = 0.f, b0 = 0.f, b1v = 0.f;
    int k = l;
    for (; k + 8 < cnt; k += 16) {
        unsigned s0 = g_srcs[start + k];
        unsigned s1 = g_srcs[start + k + 8];
        float2 h0 = *(const float2*)&g_h2[(long long)s0 * 2];
        float2 h1 = *(const float2*)&g_h2[(long long)s1 * 2];
        a0 += h0.x; a1 += h0.y;
        b0 += h1.x; b1v += h1.y;
    }
    if (k < cnt) {
        unsigned s = g_srcs[start + k];
        float2 h = *(const float2*)&g_h2[(long long)s * 2];
        a0 += h.x; a1 += h.y;
    }
    a0 += b0; a1 += b1v;
#pragma unroll
    for (int o = 4; o > 0; o >>= 1) {
        a0 += __shfl_down_sync(0xffffffffu, a0, o, 8);
        a1 += __shfl_down_sync(0xffffffffu, a1, o, 8);
    }
    if (live && l == 0) {
        float2 hs = *(const float2*)&g_h2[(long long)v * 2];
        float v0 = dv * (a0 + hs.x) + __ldg(&b2[0]);
        float v1 = dv * (a1 + hs.y) + __ldg(&b2[1]);
        float m  = fmaxf(v0, v1);
        float lse = m + logf(expf(v0 - m) + expf(v1 - m));
        out[(long long)v * 2 + 0] = v0 - lse;
        out[(long long)v * 2 + 1] = v1 - lse;
        g_cnt[v] = 0;
    }
}

extern "C" void kernel_launch(void* const* d_in, const int* in_sizes, int n_in,
                              void* d_out, int out_size) {
    const float* x  = (const float*)d_in[0];
    const void*  ei = d_in[1];
    const float* W1 = (const float*)d_in[2];
    const float* b1 = (const float*)d_in[3];
    const float* W2 = (const float*)d_in[4];
    const float* b2 = (const float*)d_in[5];
    float* out = (float*)d_out;

    int n = in_sizes[0] / DIN;
    long long e = (long long)in_sizes[1] / 2;

    int nb_e     = (int)((e + 255) / 256);
    int nb_place = (int)((e + 511) / 512);
    int nb_scan  = (n + SCAN_CHUNK - 1) / SCAN_CHUNK;
    int nb_g     = ((n + 1) / 2 + 255) / 256;
    int nb_a1    = (n * 16 + 255) / 256;
    int nb_a2    = (n * 8 + 255) / 256;

    k_prep  <<<nb_e,     256>>>(ei, e, n);
    k_scanA <<<nb_scan,  256>>>(n);
    k_scanC <<<nb_scan,  256>>>(n, nb_scan);
    k_place <<<nb_place, 256>>>(e);
    k_gemm1 <<<nb_g,     256>>>(x, W1, n);
    k_agg1  <<<nb_a1,    256>>>(b1, W2, n);
    k_agg2  <<<nb_a2,    256>>>(b2, out, n);
}

// round 9
// speedup vs baseline: 1.1287x; 1.0293x over previous
#include <cuda_runtime.h>
#include <math.h>

#define NMAX 100000
#define EMAX 3200000
#define DIN  128
#define HID  16
#define SCAN_CHUNK 512
#define MAX_SCAN_BLOCKS 1024

#define FLAG_AGG 0x40000000u
#define FLAG_INC 0x80000000u
#define VAL_MASK 0x3FFFFFFFu

// ---- scratch (device globals; allocations forbidden) ----
__device__ int      g_cnt  [NMAX];          // zeroed at end of k_agg2 for next replay
__device__ int      g_start[NMAX];
__device__ float    g_dis  [NMAX];
__device__ float    g_h1   [NMAX * HID];    // pre-scaled by dis[node]
__device__ float    g_h2   [NMAX * 2];      // pre-scaled by dis[node]
__device__ unsigned g_row  [EMAX];
__device__ unsigned g_cr   [EMAX];          // col (bits 0-16) | rank (bits 17-31)
__device__ unsigned g_srcs [EMAX];
__device__ unsigned g_state[MAX_SCAN_BLOCKS]; // decoupled-lookback state (zeroed by prep)

__device__ __forceinline__ int block_exscan256(int v) {
    __shared__ int wsum[8];
    int lane = threadIdx.x & 31, wid = threadIdx.x >> 5;
    int inc = v;
#pragma unroll
    for (int o = 1; o < 32; o <<= 1) {
        int u = __shfl_up_sync(0xffffffffu, inc, o);
        if (lane >= o) inc += u;
    }
    if (lane == 31) wsum[wid] = inc;
    __syncthreads();
    if (wid == 0) {
        int w = (lane < 8) ? wsum[lane] : 0;
        int winc = w;
#pragma unroll
        for (int o = 1; o < 32; o <<= 1) {
            int u = __shfl_up_sync(0xffffffffu, winc, o);
            if (lane >= o) winc += u;
        }
        if (lane < 8) wsum[lane] = winc - w;
    }
    __syncthreads();
    return wsum[wid] + inc - v;
}

// ---- prep: dtype vote + convert + degree histogram + rank capture + state clear ----
__global__ void __launch_bounds__(256) k_prep(const void* __restrict__ ei,
                                              long long e, int n) {
    if (blockIdx.x == 0) {           // clear lookback state for this call
        for (int j = threadIdx.x; j < MAX_SCAN_BLOCKS; j += 256) g_state[j] = 0;
    }
    long long s = ((const long long*)ei)[threadIdx.x];
    int is64 = __syncthreads_and(s >= 0 && s < n);

    long long i = blockIdx.x * 256LL + threadIdx.x;
    if (i >= e) return;
    unsigned r, c;
    if (is64) {
        r = (unsigned)((const long long*)ei)[i];
        c = (unsigned)((const long long*)ei)[e + i];
    } else {
        r = ((const unsigned*)ei)[i];
        c = ((const unsigned*)ei)[e + i];
    }
    unsigned rank = (unsigned)atomicAdd(&g_cnt[c], 1);
    g_row[i] = r;
    g_cr[i]  = c | (rank << 17);
}

// ---- merged: decoupled-lookback scan (blocks < nb_scan) || gemm1 (rest) ----
__global__ void __launch_bounds__(256) k_scan_gemm1(const float* __restrict__ x,
                                                    const float* __restrict__ W1,
                                                    int n, int nb_scan) {
    __shared__ float sW[DIN * HID];
    __shared__ int s_agg, s_excl;

    if (blockIdx.x < nb_scan) {
        int sbid = blockIdx.x;
        int base = sbid * SCAN_CHUNK;
        int t = threadIdx.x;
        int i0 = base + 2 * t;
        int c0 = (i0     < n) ? g_cnt[i0]     : 0;
        int c1 = (i0 + 1 < n) ? g_cnt[i0 + 1] : 0;
        int ex = block_exscan256(c0 + c1);
        if (t == 255) s_agg = ex + c0 + c1;
        __syncthreads();
        int agg = s_agg;

        if (sbid == 0) {
            if (t == 0) {
                atomicExch(&g_state[0], (unsigned)agg | FLAG_INC);
                s_excl = 0;
            }
        } else {
            if (t == 0) atomicExch(&g_state[sbid], (unsigned)agg | FLAG_AGG);
            if (t < 32) {            // warp 0: parallel lookback
                int lane = t;
                unsigned excl = 0;
                int idx = sbid - 1;
                while (true) {
                    int j = idx - lane;
                    unsigned sv = (j >= 0) ? *(volatile unsigned*)&g_state[j]
                                           : FLAG_INC;   // virtual block: inclusive 0
                    unsigned have = __ballot_sync(0xffffffffu, sv != 0u);
                    if (have != 0xffffffffu) continue;    // spin until published
                    unsigned incm = __ballot_sync(0xffffffffu, (sv & FLAG_INC) != 0u);
                    unsigned val = sv & VAL_MASK;
                    if (incm == 0u) {                     // all aggregates: take and step back
                        unsigned tot = val;
#pragma unroll
                        for (int o = 16; o > 0; o >>= 1)
                            tot += __shfl_down_sync(0xffffffffu, tot, o);
                        if (lane == 0) excl += tot;
                        idx -= 32;
                        continue;
                    }
                    int li = __ffs(incm) - 1;             // nearest inclusive
                    unsigned contrib = (lane <= li) ? val : 0u;
                    unsigned tot = contrib;
#pragma unroll
                    for (int o = 16; o > 0; o >>= 1)
                        tot += __shfl_down_sync(0xffffffffu, tot, o);
                    if (lane == 0) excl += tot;
                    break;
                }
                if (lane == 0) {
                    atomicExch(&g_state[sbid], (excl + (unsigned)agg) | FLAG_INC);
                    s_excl = (int)excl;
                }
            }
        }
        __syncthreads();
        int exg = ex + s_excl;
        if (i0 < n)     g_start[i0]     = exg;
        if (i0 + 1 < n) g_start[i0 + 1] = exg + c0;
        return;
    }

    // ---- gemm1 part: h1s = (x @ W1) * dis ; dis = rsqrt(cnt+1) ----
    int tid = threadIdx.x;
    for (int i = tid; i < DIN * HID; i += 256) sW[i] = W1[i];
    __syncthreads();
    int t  = (blockIdx.x - nb_scan) * 256 + tid;
    int n0 = t * 2, n1 = t * 2 + 1;
    if (n0 >= n) return;
    bool has1 = (n1 < n);
    const float4* xr0 = (const float4*)(x + (long long)n0 * DIN);
    const float4* xr1 = (const float4*)(x + (long long)(has1 ? n1 : n0) * DIN);

    float aA[HID], aB[HID];
#pragma unroll
    for (int c = 0; c < HID; c++) { aA[c] = 0.f; aB[c] = 0.f; }

#pragma unroll 4
    for (int k4 = 0; k4 < DIN / 4; k4++) {
        float4 xa = xr0[k4];
        float4 xb = xr1[k4];
        float xav[4] = {xa.x, xa.y, xa.z, xa.w};
        float xbv[4] = {xb.x, xb.y, xb.z, xb.w};
#pragma unroll
        for (int j = 0; j < 4; j++) {
            const float4* wr = (const float4*)&sW[(k4 * 4 + j) * HID];
            float4 w0 = wr[0], w1 = wr[1], w2 = wr[2], w3 = wr[3];
            float fa = xav[j], fb = xbv[j];
            aA[0] += fa*w0.x; aA[1] += fa*w0.y; aA[2] += fa*w0.z; aA[3] += fa*w0.w;
            aA[4] += fa*w1.x; aA[5] += fa*w1.y; aA[6] += fa*w1.z; aA[7] += fa*w1.w;
            aA[8] += fa*w2.x; aA[9] += fa*w2.y; aA[10]+= fa*w2.z; aA[11]+= fa*w2.w;
            aA[12]+= fa*w3.x; aA[13]+= fa*w3.y; aA[14]+= fa*w3.z; aA[15]+= fa*w3.w;
            aB[0] += fb*w0.x; aB[1] += fb*w0.y; aB[2] += fb*w0.z; aB[3] += fb*w0.w;
            aB[4] += fb*w1.x; aB[5] += fb*w1.y; aB[6] += fb*w1.z; aB[7] += fb*w1.w;
            aB[8] += fb*w2.x; aB[9] += fb*w2.y; aB[10]+= fb*w2.z; aB[11]+= fb*w2.w;
            aB[12]+= fb*w3.x; aB[13]+= fb*w3.y; aB[14]+= fb*w3.z; aB[15]+= fb*w3.w;
        }
    }

    float d0 = rsqrtf((float)(g_cnt[n0] + 1));
    g_dis[n0] = d0;
#pragma unroll
    for (int j = 0; j < 4; j++)
        *(float4*)&g_h1[(long long)n0 * HID + 4*j] =
            make_float4(aA[4*j]*d0, aA[4*j+1]*d0, aA[4*j+2]*d0, aA[4*j+3]*d0);
    if (has1) {
        float d1 = rsqrtf((float)(g_cnt[n1] + 1));
        g_dis[n1] = d1;
#pragma unroll
        for (int j = 0; j < 4; j++)
            *(float4*)&g_h1[(long long)n1 * HID + 4*j] =
                make_float4(aB[4*j]*d1, aB[4*j+1]*d1, aB[4*j+2]*d1, aB[4*j+3]*d1);
    }
}

// ---- CSR placement: no atomics, single packed index stream ----
__global__ void __launch_bounds__(256) k_place(long long e) {
    long long i = blockIdx.x * 512LL + threadIdx.x;
    if (i < e) {
        unsigned cr = g_cr[i];
        g_srcs[g_start[cr & 0x1FFFFu] + (cr >> 17)] = g_row[i];
    }
    i += 256;
    if (i < e) {
        unsigned cr = g_cr[i];
        g_srcs[g_start[cr & 0x1FFFFu] + (cr >> 17)] = g_row[i];
    }
}

// ---- layer-1 aggregation: 16 lanes/node = 4 edges x 4 col-quads, LDG.128 ----
__global__ void __launch_bounds__(256) k_agg1(const float* __restrict__ b1,
                                              const float* __restrict__ W2, int n) {
    int t = blockIdx.x * 256 + threadIdx.x;
    int v  = t >> 4;
    int l  = t & 15;
    int g  = l >> 2;
    int c4 = l & 3;
    bool live = (v < n);
    int vv = live ? v : (n - 1);

    float dv    = g_dis[vv];
    int   start = g_start[vv];
    int   cnt   = g_cnt[vv];

    float4 A = make_float4(0.f, 0.f, 0.f, 0.f);
    float4 B = make_float4(0.f, 0.f, 0.f, 0.f);
    int k = 0;
    for (; k + 8 <= cnt; k += 8) {
        unsigned s0 = g_srcs[start + k + g];
        unsigned s1 = g_srcs[start + k + 4 + g];
        float4 h0 = *(const float4*)&g_h1[(long long)s0 * HID + c4 * 4];
        float4 h1 = *(const float4*)&g_h1[(long long)s1 * HID + c4 * 4];
        A.x += h0.x; A.y += h0.y; A.z += h0.z; A.w += h0.w;
        B.x += h1.x; B.y += h1.y; B.z += h1.z; B.w += h1.w;
    }
    if (k + g < cnt) {
        unsigned s = g_srcs[start + k + g];
        float4 h = *(const float4*)&g_h1[(long long)s * HID + c4 * 4];
        A.x += h.x; A.y += h.y; A.z += h.z; A.w += h.w;
    }
    if (k + 4 + g < cnt) {
        unsigned s = g_srcs[start + k + 4 + g];
        float4 h = *(const float4*)&g_h1[(long long)s * HID + c4 * 4];
        B.x += h.x; B.y += h.y; B.z += h.z; B.w += h.w;
    }
    A.x += B.x; A.y += B.y; A.z += B.z; A.w += B.w;

#pragma unroll
    for (int o = 8; o >= 4; o >>= 1) {
        A.x += __shfl_down_sync(0xffffffffu, A.x, o, 16);
        A.y += __shfl_down_sync(0xffffffffu, A.y, o, 16);
        A.z += __shfl_down_sync(0xffffffffu, A.z, o, 16);
        A.w += __shfl_down_sync(0xffffffffu, A.w, o, 16);
    }

    float p0 = 0.f, p1 = 0.f;
    if (l < 4) {
        float4 self = *(const float4*)&g_h1[(long long)vv * HID + l * 4];
        float a0 = fmaxf(dv * (A.x + self.x) + __ldg(&b1[l*4+0]), 0.f);
        float a1 = fmaxf(dv * (A.y + self.y) + __ldg(&b1[l*4+1]), 0.f);
        float a2 = fmaxf(dv * (A.z + self.z) + __ldg(&b1[l*4+2]), 0.f);
        float a3 = fmaxf(dv * (A.w + self.w) + __ldg(&b1[l*4+3]), 0.f);
        p0 = a0*__ldg(&W2[(l*4+0)*2+0]) + a1*__ldg(&W2[(l*4+1)*2+0])
           + a2*__ldg(&W2[(l*4+2)*2+0]) + a3*__ldg(&W2[(l*4+3)*2+0]);
        p1 = a0*__ldg(&W2[(l*4+0)*2+1]) + a1*__ldg(&W2[(l*4+1)*2+1])
           + a2*__ldg(&W2[(l*4+2)*2+1]) + a3*__ldg(&W2[(l*4+3)*2+1]);
    }
    p0 += __shfl_down_sync(0xffffffffu, p0, 2, 16);
    p1 += __shfl_down_sync(0xffffffffu, p1, 2, 16);
    p0 += __shfl_down_sync(0xffffffffu, p0, 1, 16);
    p1 += __shfl_down_sync(0xffffffffu, p1, 1, 16);
    if (live && l == 0) {
        g_h2[(long long)v * 2 + 0] = p0 * dv;
        g_h2[(long long)v * 2 + 1] = p1 * dv;
    }
}

// ---- layer-2 aggregation + log_softmax; zeroes g_cnt for the next replay ----
__global__ void __launch_bounds__(256) k_agg2(const float* __restrict__ b2,
                                              float* __restrict__ out, int n) {
    int t = blockIdx.x * 256 + threadIdx.x;
    int v = t >> 3;
    int l = t & 7;
    bool live = (v < n);
    int vv = live ? v : (n - 1);

    float dv    = g_dis[vv];
    int   start = g_start[vv];
    int   cnt   = g_cnt[vv];
    float a0 = 0.f, a1 = 0.f, b0 = 0.f, b1v = 0.f;
    int k = l;
    for (; k + 8 < cnt; k += 16) {
        unsigned s0 = g_srcs[start + k];
        unsigned s1 = g_srcs[start + k + 8];
        float2 h0 = *(const float2*)&g_h2[(long long)s0 * 2];
        float2 h1 = *(const float2*)&g_h2[(long long)s1 * 2];
        a0 += h0.x; a1 += h0.y;
        b0 += h1.x; b1v += h1.y;
    }
    if (k < cnt) {
        unsigned s = g_srcs[start + k];
        float2 h = *(const float2*)&g_h2[(long long)s * 2];
        a0 += h.x; a1 += h.y;
    }
    a0 += b0; a1 += b1v;
#pragma unroll
    for (int o = 4; o > 0; o >>= 1) {
        a0 += __shfl_down_sync(0xffffffffu, a0, o, 8);
        a1 += __shfl_down_sync(0xffffffffu, a1, o, 8);
    }
    if (live && l == 0) {
        float2 hs = *(const float2*)&g_h2[(long long)v * 2];
        float v0 = dv * (a0 + hs.x) + __ldg(&b2[0]);
        float v1 = dv * (a1 + hs.y) + __ldg(&b2[1]);
        float m  = fmaxf(v0, v1);
        float lse = m + logf(expf(v0 - m) + expf(v1 - m));
        out[(long long)v * 2 + 0] = v0 - lse;
        out[(long long)v * 2 + 1] = v1 - lse;
        g_cnt[v] = 0;
    }
}

extern "C" void kernel_launch(void* const* d_in, const int* in_sizes, int n_in,
                              void* d_out, int out_size) {
    const float* x  = (const float*)d_in[0];
    const void*  ei = d_in[1];
    const float* W1 = (const float*)d_in[2];
    const float* b1 = (const float*)d_in[3];
    const float* W2 = (const float*)d_in[4];
    const float* b2 = (const float*)d_in[5];
    float* out = (float*)d_out;

    int n = in_sizes[0] / DIN;
    long long e = (long long)in_sizes[1] / 2;

    int nb_e     = (int)((e + 255) / 256);
    int nb_place = (int)((e + 511) / 512);
    int nb_scan  = (n + SCAN_CHUNK - 1) / SCAN_CHUNK;
    int nb_g     = ((n + 1) / 2 + 255) / 256;
    int nb_a1    = (n * 16 + 255) / 256;
    int nb_a2    = (n * 8 + 255) / 256;

    k_prep      <<<nb_e,            256>>>(ei, e, n);
    k_scan_gemm1<<<nb_scan + nb_g,  256>>>(x, W1, n, nb_scan);
    k_place     <<<nb_place,        256>>>(e);
    k_agg1      <<<nb_a1,           256>>>(b1, W2, n);
    k_agg2      <<<nb_a2,           256>>>(b2, out, n);
}